// round 13
// baseline (speedup 1.0000x reference)
#include <cuda_runtime.h>
#include <cuda_fp16.h>
#include <math.h>
#include <stdint.h>

// Problem constants
#define BB 8
#define SS 2048
#define DD 1024
#define AD 512
#define NQKV 1536   // 3*AD concatenated q|k|v output columns

// ---------------------------------------------------------------------------
// Scratch (__device__ globals; allocation-free rule)
// ---------------------------------------------------------------------------
__device__ float  g_gq[BB * AD];
__device__ float  g_gs[BB * SS];
__device__ float  g_gout[BB * AD];
__device__ float  g_part[BB * 16 * SS];
__device__ float  g_bqkv[NQKV];

__device__ __half g_xh[BB * SS * DD];                 // half x
__device__ __half g_wqkvt[NQKV * DD];                 // [Wq|Wk|Wv]^T half [1536][1024]
__device__ __half g_wot[DD * AD];                     // Wo^T half [D][A]
__device__ __half g_qkv[(size_t)BB * SS * NQKV];      // q|k|v interleaved [b][s][1536]
__device__ __half g_vth[BB * SS * AD];                // V^T half [b][a][s]
__device__ __half g_wh[(size_t)BB * SS * SS];         // half softmax weights
__device__ __half g_winh[BB * SS * AD];
__device__ __half g_yh[BB * SS * DD];                 // half y (residual+LN)

// ---------------------------------------------------------------------------
// fp16 tensor-core GEMM, all-NT: C[m][n] = sum_k A[m][k] * B[n][k]
// Block 128 x (NTIL*16), K-chunk 32, 128 threads (4 warps 2x2).
// Warp tile 64 x (NTIL*8). NTIL=8 -> 128x128 block; NTIL=4 -> 128x64 block.
// mma.sync.m16n8k16 fp32-accum, ldmatrix frag loads, 3-stage cp.async.
// EPI: 0 half out +e0[n]; 2 half out *scale;
//      3 half out 0.7*acc+0.3*e0[z*AD+n]; 4 half out +e0[n]+e1h[m*ldc+n]
// ---------------------------------------------------------------------------
#define HSTR 40                       // row stride in halves (80 B)
#define STG_H (128 * HSTR)            // halves per stage per operand
#define GH_SMEM (3 * STG_H * 2 * 2)   // 61440 B (3 stages, A+B, 2B/half)

__device__ __forceinline__ void cp16(void* s, const void* g) {
    uint32_t sa = (uint32_t)__cvta_generic_to_shared(s);
    asm volatile("cp.async.cg.shared.global [%0], [%1], 16;\n" :: "r"(sa), "l"(g));
}
#define LDSM4(r0, r1, r2, r3, a) \
    asm volatile("ldmatrix.sync.aligned.m8n8.x4.shared.b16 {%0,%1,%2,%3}, [%4];" \
                 : "=r"(r0), "=r"(r1), "=r"(r2), "=r"(r3) : "r"(a))

template <int EPI, int NTIL>
__global__ void __launch_bounds__(128, 3) gemm_h(
    const __half* __restrict__ Am, const __half* __restrict__ Bm,
    float* __restrict__ Cf, __half* __restrict__ Ch,
    int K, int lda, int ldb, int ldc,
    size_t sA, size_t sB, size_t sC,
    const float* __restrict__ e0, const __half* __restrict__ e1h, float scale)
{
    extern __shared__ __half sh[];
    __half* As = sh;                 // 3 stages x 128 x HSTR
    __half* Bs = sh + 3 * STG_H;

    const __half* Ap = Am + (size_t)blockIdx.z * sA;
    const __half* Bp = Bm + (size_t)blockIdx.z * sB;

    const int tid = threadIdx.x;
    const int wid = tid >> 5;
    const int lane = tid & 31;
    const int wm = wid >> 1;
    const int wn = wid & 1;
    const int g = lane >> 2;
    const int t = lane & 3;
    const int WCOLS = NTIL * 8;             // warp n-extent
    const int m0 = blockIdx.y * 128;
    const int n0 = blockIdx.x * (2 * WCOLS);

    const int lrow = lane & 15;
    const int lcol = (lane >> 4) << 3;
    const uint32_t sAb = (uint32_t)__cvta_generic_to_shared(As);
    const uint32_t sBb = (uint32_t)__cvta_generic_to_shared(Bs);
    const uint32_t stageBytes = STG_H * 2;

    float acc[4][NTIL][4];
#pragma unroll
    for (int i = 0; i < 4; i++)
#pragma unroll
        for (int j = 0; j < NTIL; j++)
#pragma unroll
            for (int c = 0; c < 4; c++) acc[i][j][c] = 0.f;

    auto copy_stage = [&](int st, int k0) {
#pragma unroll
        for (int i = 0; i < 4; i++) {
            int c = tid + 128 * i;
            int row = c >> 2, off = (c & 3) << 3;
            cp16(&As[st * STG_H + row * HSTR + off],
                 Ap + (size_t)(m0 + row) * lda + k0 + off);
        }
#pragma unroll
        for (int i = 0; i < NTIL / 2; i++) {   // B: (2*WCOLS) rows x 4 chunks
            int c = tid + 128 * i;
            int row = c >> 2, off = (c & 3) << 3;
            cp16(&Bs[st * STG_H + row * HSTR + off],
                 Bp + (size_t)(n0 + row) * ldb + k0 + off);
        }
    };

    const int nk = K / 32;
    copy_stage(0, 0);
    asm volatile("cp.async.commit_group;\n");
    copy_stage(1, 32);
    asm volatile("cp.async.commit_group;\n");

    int cur = 0;
    for (int kt = 0; kt < nk; kt++) {
        if (kt + 1 < nk) asm volatile("cp.async.wait_group 1;\n");
        else             asm volatile("cp.async.wait_group 0;\n");
        __syncthreads();
        if (kt + 2 < nk) {
            int nx = cur + 2; if (nx >= 3) nx -= 3;
            copy_stage(nx, (kt + 2) * 32);
            asm volatile("cp.async.commit_group;\n");
        }
        uint32_t aBase = sAb + cur * stageBytes + ((wm * 64 + lrow) * HSTR + lcol) * 2;
        uint32_t bBase = sBb + cur * stageBytes + ((wn * WCOLS + lrow) * HSTR + lcol) * 2;
#pragma unroll
        for (int ks = 0; ks < 2; ks++) {
            const int kb = ks * 16;
            uint32_t afr[4][4];
#pragma unroll
            for (int mt = 0; mt < 4; mt++)
                LDSM4(afr[mt][0], afr[mt][1], afr[mt][2], afr[mt][3],
                      aBase + (mt * 16 * HSTR + kb) * 2);
#pragma unroll
            for (int p = 0; p < NTIL / 2; p++) {
                uint32_t b00, b01, b10, b11;
                LDSM4(b00, b01, b10, b11, bBase + (p * 16 * HSTR + kb) * 2);
#pragma unroll
                for (int h = 0; h < 2; h++) {
                    int nt = p * 2 + h;
                    uint32_t b0 = h ? b01 : b00;
                    uint32_t b1 = h ? b11 : b10;
#pragma unroll
                    for (int mt = 0; mt < 4; mt++) {
                        asm volatile(
                            "mma.sync.aligned.m16n8k16.row.col.f32.f16.f16.f32 "
                            "{%0,%1,%2,%3}, {%4,%5,%6,%7}, {%8,%9}, {%0,%1,%2,%3};\n"
                            : "+f"(acc[mt][nt][0]), "+f"(acc[mt][nt][1]),
                              "+f"(acc[mt][nt][2]), "+f"(acc[mt][nt][3])
                            : "r"(afr[mt][0]), "r"(afr[mt][1]),
                              "r"(afr[mt][2]), "r"(afr[mt][3]),
                              "r"(b0), "r"(b1));
                    }
                }
            }
        }
        if (++cur == 3) cur = 0;
    }

    // Epilogue (C frag: c0,c1 = row g cols 2t,2t+1; c2,c3 = row g+8)
#pragma unroll
    for (int mt = 0; mt < 4; mt++) {
#pragma unroll
        for (int nt = 0; nt < NTIL; nt++) {
            int row = m0 + wm * 64 + mt * 16 + g;
            int col = n0 + wn * WCOLS + nt * 8 + 2 * t;
#pragma unroll
            for (int h = 0; h < 2; h++) {
                int r = row + h * 8;
                float v0 = acc[mt][nt][h * 2 + 0];
                float v1 = acc[mt][nt][h * 2 + 1];
                if (EPI == 0) {
                    v0 += e0[col]; v1 += e0[col + 1];
                    __half* Cp = Ch + (size_t)blockIdx.z * sC;
                    *(__half2*)&Cp[(size_t)r * ldc + col] = __floats2half2_rn(v0, v1);
                } else if (EPI == 2) {
                    __half* Cp = Ch + (size_t)blockIdx.z * sC;
                    *(__half2*)&Cp[(size_t)r * ldc + col] =
                        __floats2half2_rn(v0 * scale, v1 * scale);
                } else if (EPI == 3) {
                    v0 = 0.7f * v0 + 0.3f * e0[blockIdx.z * AD + col];
                    v1 = 0.7f * v1 + 0.3f * e0[blockIdx.z * AD + col + 1];
                    __half* Cp = Ch + (size_t)blockIdx.z * sC;
                    *(__half2*)&Cp[(size_t)r * ldc + col] = __floats2half2_rn(v0, v1);
                } else {
                    __half2 res = *(const __half2*)&e1h[(size_t)r * ldc + col];
                    float2 rf = __half22float2(res);
                    v0 += e0[col]     + rf.x;
                    v1 += e0[col + 1] + rf.y;
                    __half* Cp = Ch + (size_t)blockIdx.z * sC;
                    *(__half2*)&Cp[(size_t)r * ldc + col] = __floats2half2_rn(v0, v1);
                }
            }
        }
    }
}

// ---------------------------------------------------------------------------
// Prep: x f32 -> half AND concat bias vectors (first blocks)
// ---------------------------------------------------------------------------
__global__ void __launch_bounds__(256) k_prep(
    const float4* __restrict__ in, __half* __restrict__ out,
    const float* __restrict__ bq, const float* __restrict__ bk,
    const float* __restrict__ bv, float* __restrict__ bout)
{
    int i = blockIdx.x * 256 + threadIdx.x;
    float4 v = in[i];
    __half2* o = (__half2*)(out + (size_t)i * 4);
    o[0] = __floats2half2_rn(v.x, v.y);
    o[1] = __floats2half2_rn(v.z, v.w);
    if (i < NQKV) {
        float b = (i < AD) ? bq[i] : (i < 2 * AD) ? bk[i - AD] : bv[i - 2 * AD];
        bout[i] = b;
    }
}

// ---------------------------------------------------------------------------
// Transpose + convert: src f32 [R][C] -> dst half [C][R].  block (32,8)
// ---------------------------------------------------------------------------
__global__ void k_transpose_h(const float* __restrict__ src, __half* __restrict__ dst,
                              int R, int C)
{
    __shared__ float t[32][33];
    int c0 = blockIdx.x * 32, r0 = blockIdx.y * 32;
    int tx = threadIdx.x, ty = threadIdx.y;
#pragma unroll
    for (int i = 0; i < 32; i += 8)
        t[ty + i][tx] = src[(size_t)(r0 + ty + i) * C + c0 + tx];
    __syncthreads();
#pragma unroll
    for (int i = 0; i < 32; i += 8)
        dst[(size_t)(c0 + ty + i) * R + r0 + tx] = __float2half(t[tx][ty + i]);
}

// ---------------------------------------------------------------------------
// Half transpose: src half [R][srcLd] (+batch) -> dst half [C][R] (+batch)
// ---------------------------------------------------------------------------
__global__ void k_transpose_hh(const __half* __restrict__ src, __half* __restrict__ dst,
                               int R, int C, int srcLd, size_t sSrc, size_t sDst)
{
    __shared__ __half t[32][34];
    src += (size_t)blockIdx.z * sSrc;
    dst += (size_t)blockIdx.z * sDst;
    int c0 = blockIdx.x * 32, r0 = blockIdx.y * 32;
    int tx = threadIdx.x, ty = threadIdx.y;
#pragma unroll
    for (int i = 0; i < 32; i += 8)
        t[ty + i][tx] = src[(size_t)(r0 + ty + i) * srcLd + c0 + tx];
    __syncthreads();
#pragma unroll
    for (int i = 0; i < 32; i += 8)
        dst[(size_t)(c0 + ty + i) * R + r0 + tx] = t[tx][ty + i];
}

// ---------------------------------------------------------------------------
// gq two-stage (fp32 Wq)
// ---------------------------------------------------------------------------
__global__ void __launch_bounds__(128) k_gq_part(
    const float* __restrict__ gc, const float* __restrict__ W, float* __restrict__ part)
{
    int a = blockIdx.x * 128 + threadIdx.x;
    int dc = blockIdx.y, b = blockIdx.z;
    const float* gv = gc + (size_t)b * DD + dc * 128;
    const float* Wp = W + (size_t)(dc * 128) * AD + a;
    float s = 0.f;
#pragma unroll 4
    for (int d = 0; d < 128; d++) s += gv[d] * Wp[(size_t)d * AD];
    part[((size_t)b * 8 + dc) * AD + a] = s;
}
__global__ void __launch_bounds__(128) k_gq_red(
    const float* __restrict__ part, const float* __restrict__ bias, float* __restrict__ gq)
{
    int a = blockIdx.x * 128 + threadIdx.x;
    int b = blockIdx.y;
    float s = bias[a];
#pragma unroll
    for (int j = 0; j < 8; j++) s += part[((size_t)b * 8 + j) * AD + a];
    gq[b * AD + a] = s;
}

// ---------------------------------------------------------------------------
// gscores[b,s] = dot(gq[b,:], k[b,s,:]) / sqrt(AD)  (k inside qkv, stride 1536)
// ---------------------------------------------------------------------------
__global__ void __launch_bounds__(256) k_gscores(
    const __half* __restrict__ qkv, const float* __restrict__ gq, float* __restrict__ gs)
{
    int t = threadIdx.x;
    int key = blockIdx.x * 32 + (t >> 3);
    int lane = t & 7;
    int b = key / SS;
    int s = key % SS;
    const __half* krow = qkv + (size_t)key * NQKV + AD;
    const float* q = gq + b * AD;
    float sum = 0.f;
    for (int a = lane; a < AD; a += 8) sum += __half2float(krow[a]) * q[a];
#pragma unroll
    for (int o = 4; o > 0; o >>= 1) sum += __shfl_down_sync(0xffffffffu, sum, o, 8);
    if (lane == 0) gs[b * SS + s] = sum * rsqrtf((float)AD);
}

// ---------------------------------------------------------------------------
// In-place half softmax, rows of SS=2048. 256 threads; 8 halves/thread.
// ---------------------------------------------------------------------------
__global__ void __launch_bounds__(256) k_softmax_h(__half* __restrict__ data)
{
    uint4* row = (uint4*)(data + (size_t)blockIdx.x * SS);
    int t = threadIdx.x;
    uint4 u = row[t];
    __half2 h[4];
    memcpy(h, &u, 16);
    float v[8];
#pragma unroll
    for (int i = 0; i < 4; i++) {
        float2 f = __half22float2(h[i]);
        v[2 * i] = f.x; v[2 * i + 1] = f.y;
    }
    __shared__ float red[8];

    float m = v[0];
#pragma unroll
    for (int i = 1; i < 8; i++) m = fmaxf(m, v[i]);
#pragma unroll
    for (int o = 16; o > 0; o >>= 1) m = fmaxf(m, __shfl_xor_sync(0xffffffffu, m, o));
    if ((t & 31) == 0) red[t >> 5] = m;
    __syncthreads();
    m = red[0];
#pragma unroll
    for (int w = 1; w < 8; w++) m = fmaxf(m, red[w]);
    __syncthreads();

    float s = 0.f;
#pragma unroll
    for (int i = 0; i < 8; i++) { v[i] = __expf(v[i] - m); s += v[i]; }
#pragma unroll
    for (int o = 16; o > 0; o >>= 1) s += __shfl_xor_sync(0xffffffffu, s, o);
    if ((t & 31) == 0) red[t >> 5] = s;
    __syncthreads();
    float tot = 0.f;
#pragma unroll
    for (int w = 0; w < 8; w++) tot += red[w];
    float inv = 1.f / tot;

#pragma unroll
    for (int i = 0; i < 4; i++)
        h[i] = __floats2half2_rn(v[2 * i] * inv, v[2 * i + 1] * inv);
    memcpy(&u, h, 16);
    row[t] = u;
}

// ---------------------------------------------------------------------------
// fp32 softmax (for the tiny global-scores rows)
// ---------------------------------------------------------------------------
__global__ void __launch_bounds__(256) k_softmax_f(float* __restrict__ data)
{
    float4* row = (float4*)(data + (size_t)blockIdx.x * SS);
    int t = threadIdx.x;
    float4 v0 = row[t];
    float4 v1 = row[t + 256];
    __shared__ float red[8];

    float m = fmaxf(fmaxf(fmaxf(v0.x, v0.y), fmaxf(v0.z, v0.w)),
                    fmaxf(fmaxf(v1.x, v1.y), fmaxf(v1.z, v1.w)));
#pragma unroll
    for (int o = 16; o > 0; o >>= 1) m = fmaxf(m, __shfl_xor_sync(0xffffffffu, m, o));
    if ((t & 31) == 0) red[t >> 5] = m;
    __syncthreads();
    m = red[0];
#pragma unroll
    for (int w = 1; w < 8; w++) m = fmaxf(m, red[w]);
    __syncthreads();

    v0.x = __expf(v0.x - m); v0.y = __expf(v0.y - m);
    v0.z = __expf(v0.z - m); v0.w = __expf(v0.w - m);
    v1.x = __expf(v1.x - m); v1.y = __expf(v1.y - m);
    v1.z = __expf(v1.z - m); v1.w = __expf(v1.w - m);

    float s = (v0.x + v0.y + v0.z + v0.w) + (v1.x + v1.y + v1.z + v1.w);
#pragma unroll
    for (int o = 16; o > 0; o >>= 1) s += __shfl_xor_sync(0xffffffffu, s, o);
    if ((t & 31) == 0) red[t >> 5] = s;
    __syncthreads();
    float tot = 0.f;
#pragma unroll
    for (int w = 0; w < 8; w++) tot += red[w];
    float inv = 1.f / tot;

    v0.x *= inv; v0.y *= inv; v0.z *= inv; v0.w *= inv;
    v1.x *= inv; v1.y *= inv; v1.z *= inv; v1.w *= inv;
    row[t] = v0;
    row[t + 256] = v1;
}

// ---------------------------------------------------------------------------
// global_out two-stage (half v inside qkv, stride 1536)
// ---------------------------------------------------------------------------
__global__ void __launch_bounds__(128) k_gout_part(
    const float* __restrict__ gw, const __half* __restrict__ qkv, float* __restrict__ part)
{
    int a = blockIdx.x * 128 + threadIdx.x;
    int sc = blockIdx.y, b = blockIdx.z;
    const __half* vb = qkv + (size_t)b * SS * NQKV + (size_t)(sc * 128) * NQKV + 2 * AD + a;
    const float* w = gw + b * SS + sc * 128;
    float sum = 0.f;
#pragma unroll 4
    for (int s = 0; s < 128; s++) sum += w[s] * __half2float(vb[(size_t)s * NQKV]);
    part[((size_t)b * 16 + sc) * AD + a] = sum;
}
__global__ void __launch_bounds__(128) k_gout_red(
    const float* __restrict__ part, float* __restrict__ go)
{
    int a = blockIdx.x * 128 + threadIdx.x;
    int b = blockIdx.y;
    float s = 0.f;
#pragma unroll
    for (int j = 0; j < 16; j++) s += part[((size_t)b * 16 + j) * AD + a];
    go[b * AD + a] = s;
}

// ---------------------------------------------------------------------------
// LayerNorm in-place on HALF rows (len DD). 256 threads, 4 halves/thread.
// ---------------------------------------------------------------------------
__global__ void __launch_bounds__(256) k_ln_h(
    __half* __restrict__ y, const float* __restrict__ gamma, const float* __restrict__ beta)
{
    __half2* row = (__half2*)(y + (size_t)blockIdx.x * DD);
    int t = threadIdx.x;
    __half2 a = row[t];
    __half2 b = row[t + 256];
    float2 fa = __half22float2(a);
    float2 fb = __half22float2(b);
    float sum = fa.x + fa.y + fb.x + fb.y;
    float sq = fa.x * fa.x + fa.y * fa.y + fb.x * fb.x + fb.y * fb.y;

    __shared__ float r1[8], r2[8];
#pragma unroll
    for (int o = 16; o > 0; o >>= 1) {
        sum += __shfl_xor_sync(0xffffffffu, sum, o);
        sq += __shfl_xor_sync(0xffffffffu, sq, o);
    }
    if ((t & 31) == 0) { r1[t >> 5] = sum; r2[t >> 5] = sq; }
    __syncthreads();
    float ts = 0.f, tq = 0.f;
#pragma unroll
    for (int w = 0; w < 8; w++) { ts += r1[w]; tq += r2[w]; }
    float mu = ts * (1.f / DD);
    float var = tq * (1.f / DD) - mu * mu;
    float inv = rsqrtf(var + 1e-5f);

    int c0 = 2 * t, c1 = 2 * (t + 256);
    row[t] = __floats2half2_rn((fa.x - mu) * inv * gamma[c0] + beta[c0],
                               (fa.y - mu) * inv * gamma[c0 + 1] + beta[c0 + 1]);
    row[t + 256] = __floats2half2_rn((fb.x - mu) * inv * gamma[c1] + beta[c1],
                                     (fb.y - mu) * inv * gamma[c1 + 1] + beta[c1 + 1]);
}

// ---------------------------------------------------------------------------
// colmean two-stage (HALF weights -> fp32 partials)
// ---------------------------------------------------------------------------
__global__ void __launch_bounds__(256) k_colmean_part(
    const __half* __restrict__ wts, float* __restrict__ part)
{
    int s = blockIdx.x * 256 + threadIdx.x;
    int qc = blockIdx.y, b = blockIdx.z;
    const __half* base = wts + (size_t)b * SS * SS + (size_t)(qc * 256) * SS + s;
    float sum = 0.f;
#pragma unroll 4
    for (int q = 0; q < 256; q++) sum += __half2float(base[(size_t)q * SS]);
    part[((size_t)b * 8 + qc) * SS + s] = sum;
}
__global__ void __launch_bounds__(256) k_colmean_red(
    const float* __restrict__ part, const float* __restrict__ gw, float* __restrict__ avg)
{
    int s = blockIdx.x * 256 + threadIdx.x;
    int b = blockIdx.y;
    float sum = 0.f;
#pragma unroll
    for (int j = 0; j < 8; j++) sum += part[((size_t)b * 8 + j) * SS + s];
    avg[b * SS + s] = 0.7f * (sum * (1.f / SS)) + 0.3f * gw[b * SS + s];
}

// ---------------------------------------------------------------------------
// context two-stage (HALF y)
// ---------------------------------------------------------------------------
__global__ void __launch_bounds__(256) k_context_part(
    const float* __restrict__ avg, const __half* __restrict__ y, float* __restrict__ part)
{
    int d = blockIdx.x * 256 + threadIdx.x;
    int sc = blockIdx.y, b = blockIdx.z;
    const __half* yb = y + (size_t)b * SS * DD + (size_t)(sc * 128) * DD + d;
    const float* w = avg + b * SS + sc * 128;
    float sum = 0.f;
#pragma unroll 4
    for (int s = 0; s < 128; s++) sum += w[s] * __half2float(yb[(size_t)s * DD]);
    part[((size_t)b * 16 + sc) * DD + d] = sum;
}
__global__ void __launch_bounds__(256) k_context_red(
    const float* __restrict__ part, float* __restrict__ ctx)
{
    int d = blockIdx.x * 256 + threadIdx.x;
    int b = blockIdx.y;
    float s = 0.f;
#pragma unroll
    for (int j = 0; j < 16; j++) s += part[((size_t)b * 16 + j) * DD + d];
    ctx[b * DD + d] = s;
}

// ---------------------------------------------------------------------------

extern "C" void kernel_launch(void* const* d_in, const int* in_sizes, int n_in,
                              void* d_out, int out_size)
{
    const float* x     = (const float*)d_in[0];
    const float* gc    = (const float*)d_in[1];
    const float* Wq    = (const float*)d_in[2];
    const float* bq    = (const float*)d_in[3];
    const float* Wk    = (const float*)d_in[4];
    const float* bk    = (const float*)d_in[5];
    const float* Wv    = (const float*)d_in[6];
    const float* bv    = (const float*)d_in[7];
    const float* Wo    = (const float*)d_in[8];
    const float* bo    = (const float*)d_in[9];
    const float* gamma = (const float*)d_in[10];
    const float* beta  = (const float*)d_in[11];
    float* outp = (float*)d_out;

    float *pgq, *pgs, *pgo, *ppart, *pbqkv;
    __half *pxh, *pwqkvt, *pwot, *pqkv, *pvth, *pwh, *pwinh, *pyh;
    cudaGetSymbolAddress((void**)&pgq,   g_gq);
    cudaGetSymbolAddress((void**)&pgs,   g_gs);
    cudaGetSymbolAddress((void**)&pgo,   g_gout);
    cudaGetSymbolAddress((void**)&ppart, g_part);
    cudaGetSymbolAddress((void**)&pbqkv, g_bqkv);
    cudaGetSymbolAddress((void**)&pxh,   g_xh);
    cudaGetSymbolAddress((void**)&pwqkvt, g_wqkvt);
    cudaGetSymbolAddress((void**)&pwot,  g_wot);
    cudaGetSymbolAddress((void**)&pqkv,  g_qkv);
    cudaGetSymbolAddress((void**)&pvth,  g_vth);
    cudaGetSymbolAddress((void**)&pwh,   g_wh);
    cudaGetSymbolAddress((void**)&pwinh, g_winh);
    cudaGetSymbolAddress((void**)&pyh,   g_yh);

    cudaFuncSetAttribute((const void*)gemm_h<0, 8>, cudaFuncAttributeMaxDynamicSharedMemorySize, GH_SMEM);
    cudaFuncSetAttribute((const void*)gemm_h<2, 8>, cudaFuncAttributeMaxDynamicSharedMemorySize, GH_SMEM);
    cudaFuncSetAttribute((const void*)gemm_h<3, 4>, cudaFuncAttributeMaxDynamicSharedMemorySize, GH_SMEM);
    cudaFuncSetAttribute((const void*)gemm_h<4, 8>, cudaFuncAttributeMaxDynamicSharedMemorySize, GH_SMEM);

    const float scl = 1.0f / sqrtf((float)AD);
    const size_t strQKV = (size_t)SS * NQKV;
    const size_t strBSA = (size_t)SS * AD;
    const size_t strBSS = (size_t)SS * SS;

    // prep (x->half + bias concat) and weight transposes
    k_prep<<<(BB * SS * DD) / 1024, 256>>>((const float4*)x, pxh, bq, bk, bv, pbqkv);
    k_transpose_h<<<dim3(AD / 32, DD / 32), dim3(32, 8)>>>(Wq, pwqkvt, DD, AD);
    k_transpose_h<<<dim3(AD / 32, DD / 32), dim3(32, 8)>>>(Wk, pwqkvt + (size_t)AD * DD, DD, AD);
    k_transpose_h<<<dim3(AD / 32, DD / 32), dim3(32, 8)>>>(Wv, pwqkvt + (size_t)2 * AD * DD, DD, AD);

    // fused QKV projection: [16384,1024] x [1536,1024]^T -> qkv half
    gemm_h<0, 8><<<dim3(NQKV / 128, (BB * SS) / 128, 1), 128, GH_SMEM>>>(
        pxh, pwqkvt, nullptr, pqkv, DD, DD, DD, NQKV, 0, 0, 0, pbqkv, nullptr, 0.f);

    // Wo transpose
    k_transpose_h<<<dim3(DD / 32, AD / 32), dim3(32, 8)>>>(Wo, pwot, AD, DD);

    // v (half, inside qkv) -> vT half [a][s] per batch
    k_transpose_hh<<<dim3(AD / 32, SS / 32, BB), dim3(32, 8)>>>(
        pqkv + 2 * AD, pvth, SS, AD, NQKV, strQKV, strBSA);

    // global query projection (fp32)
    k_gq_part<<<dim3(AD / 128, 8, BB), 128>>>(gc, Wq, ppart);
    k_gq_red<<<dim3(AD / 128, BB), 128>>>(ppart, bq, pgq);

    // scores = q @ k^T / sqrt(A)  -> half
    gemm_h<2, 8><<<dim3(SS / 128, SS / 128, BB), 128, GH_SMEM>>>(
        pqkv, pqkv + AD, nullptr, pwh, AD, NQKV, NQKV, SS, strQKV, strQKV, strBSS,
        nullptr, nullptr, scl);

    // softmax in place on half scores
    k_softmax_h<<<BB * SS, 256>>>(pwh);

    // global scores + softmax (fp32)
    k_gscores<<<(BB * SS) / 32, 256>>>(pqkv, pgq, pgs);
    k_softmax_f<<<BB, 256>>>(pgs);

    // global_out (half v)
    k_gout_part<<<dim3(AD / 128, 16, BB), 128>>>(pgs, pqkv, ppart);
    k_gout_red<<<dim3(AD / 128, BB), 128>>>(ppart, pgo);

    // win = 0.7*weights@v + 0.3*gout  (128x64 tile: better wave fit, 1024 CTAs)
    gemm_h<3, 4><<<dim3(AD / 64, SS / 128, BB), 128, GH_SMEM>>>(
        pwh, pvth, nullptr, pwinh, SS, SS, SS, AD, strBSS, strBSA, strBSA,
        pgo, nullptr, 0.f);

    // y = x + win @ Wo + bo   (half out, half residual)
    gemm_h<4, 8><<<dim3(DD / 128, (BB * SS) / 128, 1), 128, GH_SMEM>>>(
        pwinh, pwot, nullptr, pyh, AD, AD, AD, DD, 0, 0, 0, bo, pxh, 0.f);

    // LayerNorm (half in/out)
    k_ln_h<<<BB * SS, 256>>>(pyh, gamma, beta);

    // avg_w (half weights)
    k_colmean_part<<<dim3(SS / 256, 8, BB), 256>>>(pwh, ppart);
    k_colmean_red<<<dim3(SS / 256, BB), 256>>>(ppart, pgs, outp + BB * DD);

    // context (half y)
    k_context_part<<<dim3(DD / 256, 16, BB), 256>>>(outp + BB * DD, pyh, ppart);
    k_context_red<<<dim3(DD / 256, BB), 256>>>(ppart, outp);
}

// round 14
// speedup vs baseline: 1.0197x; 1.0197x over previous
#include <cuda_runtime.h>
#include <cuda_fp16.h>
#include <math.h>
#include <stdint.h>

// Problem constants
#define BB 8
#define SS 2048
#define DD 1024
#define AD 512
#define NQKV 1536   // 3*AD concatenated q|k|v output columns

// ---------------------------------------------------------------------------
// Scratch (__device__ globals; allocation-free rule)
// ---------------------------------------------------------------------------
__device__ float  g_gq[BB * AD];
__device__ float  g_gs[BB * SS];
__device__ float  g_gout[BB * AD];
__device__ float  g_part[BB * 16 * SS];
__device__ float  g_bqkv[NQKV];

__device__ __half g_xh[BB * SS * DD];                 // half x
__device__ __half g_wqkvt[NQKV * DD];                 // [Wq|Wk|Wv]^T half [1536][1024]
__device__ __half g_wot[DD * AD];                     // Wo^T half [D][A]
__device__ __half g_qkv[(size_t)BB * SS * NQKV];      // q|k|v interleaved [b][s][1536]
__device__ __half g_vth[BB * SS * AD];                // V^T half [b][a][s]
__device__ __half g_wh[(size_t)BB * SS * SS];         // half softmax weights
__device__ __half g_winh[BB * SS * AD];
__device__ __half g_yh[BB * SS * DD];                 // half y (residual+LN)

// ---------------------------------------------------------------------------
// fp16 tensor-core GEMM, all-NT: C[m][n] = sum_k A[m][k] * B[n][k]
// Block 128x128, K-chunk 32, 128 threads (4 warps 2x2, warp tile 64x64).
// mma.sync.m16n8k16 fp32-accum, ldmatrix frag loads, 3-stage cp.async.
// (R12 GEMM config exactly — proven best. R13's 128x64 win-tile reverted.)
// EPI: 0 half out +e0[n]; 2 half out *scale;
//      3 half out 0.7*acc+0.3*e0[z*AD+n]; 4 half out +e0[n]+e1h[m*ldc+n]
// ---------------------------------------------------------------------------
#define HSTR 40                       // row stride in halves (80 B)
#define STG_H (128 * HSTR)            // halves per stage per operand
#define GH_SMEM (3 * STG_H * 2 * 2)   // 61440 B (3 stages, A+B, 2B/half)

__device__ __forceinline__ void cp16(void* s, const void* g) {
    uint32_t sa = (uint32_t)__cvta_generic_to_shared(s);
    asm volatile("cp.async.cg.shared.global [%0], [%1], 16;\n" :: "r"(sa), "l"(g));
}
#define LDSM4(r0, r1, r2, r3, a) \
    asm volatile("ldmatrix.sync.aligned.m8n8.x4.shared.b16 {%0,%1,%2,%3}, [%4];" \
                 : "=r"(r0), "=r"(r1), "=r"(r2), "=r"(r3) : "r"(a))

template <int EPI>
__global__ void __launch_bounds__(128, 3) gemm_h(
    const __half* __restrict__ Am, const __half* __restrict__ Bm,
    __half* __restrict__ Ch,
    int K, int lda, int ldb, int ldc,
    size_t sA, size_t sB, size_t sC,
    const float* __restrict__ e0, const __half* __restrict__ e1h, float scale)
{
    extern __shared__ __half sh[];
    __half* As = sh;                 // 3 stages x 128 x HSTR
    __half* Bs = sh + 3 * STG_H;

    const __half* Ap = Am + (size_t)blockIdx.z * sA;
    const __half* Bp = Bm + (size_t)blockIdx.z * sB;

    const int tid = threadIdx.x;
    const int wid = tid >> 5;
    const int lane = tid & 31;
    const int wm = wid >> 1;
    const int wn = wid & 1;
    const int g = lane >> 2;
    const int t = lane & 3;
    const int m0 = blockIdx.y * 128;
    const int n0 = blockIdx.x * 128;

    const int lrow = lane & 15;
    const int lcol = (lane >> 4) << 3;
    const uint32_t sAb = (uint32_t)__cvta_generic_to_shared(As);
    const uint32_t sBb = (uint32_t)__cvta_generic_to_shared(Bs);
    const uint32_t stageBytes = STG_H * 2;

    float acc[4][8][4];
#pragma unroll
    for (int i = 0; i < 4; i++)
#pragma unroll
        for (int j = 0; j < 8; j++)
#pragma unroll
            for (int c = 0; c < 4; c++) acc[i][j][c] = 0.f;

    auto copy_stage = [&](int st, int k0) {
#pragma unroll
        for (int i = 0; i < 4; i++) {
            int c = tid + 128 * i;
            int row = c >> 2, off = (c & 3) << 3;
            cp16(&As[st * STG_H + row * HSTR + off],
                 Ap + (size_t)(m0 + row) * lda + k0 + off);
        }
#pragma unroll
        for (int i = 0; i < 4; i++) {
            int c = tid + 128 * i;
            int row = c >> 2, off = (c & 3) << 3;
            cp16(&Bs[st * STG_H + row * HSTR + off],
                 Bp + (size_t)(n0 + row) * ldb + k0 + off);
        }
    };

    const int nk = K / 32;
    copy_stage(0, 0);
    asm volatile("cp.async.commit_group;\n");
    copy_stage(1, 32);
    asm volatile("cp.async.commit_group;\n");

    int cur = 0;
    for (int kt = 0; kt < nk; kt++) {
        if (kt + 1 < nk) asm volatile("cp.async.wait_group 1;\n");
        else             asm volatile("cp.async.wait_group 0;\n");
        __syncthreads();
        if (kt + 2 < nk) {
            int nx = cur + 2; if (nx >= 3) nx -= 3;
            copy_stage(nx, (kt + 2) * 32);
            asm volatile("cp.async.commit_group;\n");
        }
        uint32_t aBase = sAb + cur * stageBytes + ((wm * 64 + lrow) * HSTR + lcol) * 2;
        uint32_t bBase = sBb + cur * stageBytes + ((wn * 64 + lrow) * HSTR + lcol) * 2;
#pragma unroll
        for (int ks = 0; ks < 2; ks++) {
            const int kb = ks * 16;
            uint32_t afr[4][4];
#pragma unroll
            for (int mt = 0; mt < 4; mt++)
                LDSM4(afr[mt][0], afr[mt][1], afr[mt][2], afr[mt][3],
                      aBase + (mt * 16 * HSTR + kb) * 2);
#pragma unroll
            for (int p = 0; p < 4; p++) {
                uint32_t b00, b01, b10, b11;
                LDSM4(b00, b01, b10, b11, bBase + (p * 16 * HSTR + kb) * 2);
#pragma unroll
                for (int h = 0; h < 2; h++) {
                    int nt = p * 2 + h;
                    uint32_t b0 = h ? b01 : b00;
                    uint32_t b1 = h ? b11 : b10;
#pragma unroll
                    for (int mt = 0; mt < 4; mt++) {
                        asm volatile(
                            "mma.sync.aligned.m16n8k16.row.col.f32.f16.f16.f32 "
                            "{%0,%1,%2,%3}, {%4,%5,%6,%7}, {%8,%9}, {%0,%1,%2,%3};\n"
                            : "+f"(acc[mt][nt][0]), "+f"(acc[mt][nt][1]),
                              "+f"(acc[mt][nt][2]), "+f"(acc[mt][nt][3])
                            : "r"(afr[mt][0]), "r"(afr[mt][1]),
                              "r"(afr[mt][2]), "r"(afr[mt][3]),
                              "r"(b0), "r"(b1));
                    }
                }
            }
        }
        if (++cur == 3) cur = 0;
    }

    // Epilogue (C frag: c0,c1 = row g cols 2t,2t+1; c2,c3 = row g+8)
#pragma unroll
    for (int mt = 0; mt < 4; mt++) {
#pragma unroll
        for (int nt = 0; nt < 8; nt++) {
            int row = m0 + wm * 64 + mt * 16 + g;
            int col = n0 + wn * 64 + nt * 8 + 2 * t;
#pragma unroll
            for (int h = 0; h < 2; h++) {
                int r = row + h * 8;
                float v0 = acc[mt][nt][h * 2 + 0];
                float v1 = acc[mt][nt][h * 2 + 1];
                __half* Cp = Ch + (size_t)blockIdx.z * sC;
                if (EPI == 0) {
                    v0 += e0[col]; v1 += e0[col + 1];
                } else if (EPI == 2) {
                    v0 *= scale; v1 *= scale;
                } else if (EPI == 3) {
                    v0 = 0.7f * v0 + 0.3f * e0[blockIdx.z * AD + col];
                    v1 = 0.7f * v1 + 0.3f * e0[blockIdx.z * AD + col + 1];
                } else {
                    __half2 res = *(const __half2*)&e1h[(size_t)r * ldc + col];
                    float2 rf = __half22float2(res);
                    v0 += e0[col]     + rf.x;
                    v1 += e0[col + 1] + rf.y;
                }
                *(__half2*)&Cp[(size_t)r * ldc + col] = __floats2half2_rn(v0, v1);
            }
        }
    }
}

// ---------------------------------------------------------------------------
// Prep: x f32 -> half AND concat bias vectors (first blocks)
// ---------------------------------------------------------------------------
__global__ void __launch_bounds__(256) k_prep(
    const float4* __restrict__ in, __half* __restrict__ out,
    const float* __restrict__ bq, const float* __restrict__ bk,
    const float* __restrict__ bv, float* __restrict__ bout)
{
    int i = blockIdx.x * 256 + threadIdx.x;
    float4 v = in[i];
    __half2* o = (__half2*)(out + (size_t)i * 4);
    o[0] = __floats2half2_rn(v.x, v.y);
    o[1] = __floats2half2_rn(v.z, v.w);
    if (i < NQKV) {
        float b = (i < AD) ? bq[i] : (i < 2 * AD) ? bk[i - AD] : bv[i - 2 * AD];
        bout[i] = b;
    }
}

// ---------------------------------------------------------------------------
// Transpose + convert: src f32 [R][C] -> dst half [C][R].  block (32,8)
// ---------------------------------------------------------------------------
__global__ void k_transpose_h(const float* __restrict__ src, __half* __restrict__ dst,
                              int R, int C)
{
    __shared__ float t[32][33];
    int c0 = blockIdx.x * 32, r0 = blockIdx.y * 32;
    int tx = threadIdx.x, ty = threadIdx.y;
#pragma unroll
    for (int i = 0; i < 32; i += 8)
        t[ty + i][tx] = src[(size_t)(r0 + ty + i) * C + c0 + tx];
    __syncthreads();
#pragma unroll
    for (int i = 0; i < 32; i += 8)
        dst[(size_t)(c0 + ty + i) * R + r0 + tx] = __float2half(t[tx][ty + i]);
}

// ---------------------------------------------------------------------------
// Half transpose: src half [R][srcLd] (+batch) -> dst half [C][R] (+batch)
// ---------------------------------------------------------------------------
__global__ void k_transpose_hh(const __half* __restrict__ src, __half* __restrict__ dst,
                               int R, int C, int srcLd, size_t sSrc, size_t sDst)
{
    __shared__ __half t[32][34];
    src += (size_t)blockIdx.z * sSrc;
    dst += (size_t)blockIdx.z * sDst;
    int c0 = blockIdx.x * 32, r0 = blockIdx.y * 32;
    int tx = threadIdx.x, ty = threadIdx.y;
#pragma unroll
    for (int i = 0; i < 32; i += 8)
        t[ty + i][tx] = src[(size_t)(r0 + ty + i) * srcLd + c0 + tx];
    __syncthreads();
#pragma unroll
    for (int i = 0; i < 32; i += 8)
        dst[(size_t)(c0 + ty + i) * R + r0 + tx] = t[tx][ty + i];
}

// ---------------------------------------------------------------------------
// gq two-stage (fp32 Wq)
// ---------------------------------------------------------------------------
__global__ void __launch_bounds__(128) k_gq_part(
    const float* __restrict__ gc, const float* __restrict__ W, float* __restrict__ part)
{
    int a = blockIdx.x * 128 + threadIdx.x;
    int dc = blockIdx.y, b = blockIdx.z;
    const float* gv = gc + (size_t)b * DD + dc * 128;
    const float* Wp = W + (size_t)(dc * 128) * AD + a;
    float s = 0.f;
#pragma unroll 4
    for (int d = 0; d < 128; d++) s += gv[d] * Wp[(size_t)d * AD];
    part[((size_t)b * 8 + dc) * AD + a] = s;
}
__global__ void __launch_bounds__(128) k_gq_red(
    const float* __restrict__ part, const float* __restrict__ bias, float* __restrict__ gq)
{
    int a = blockIdx.x * 128 + threadIdx.x;
    int b = blockIdx.y;
    float s = bias[a];
#pragma unroll
    for (int j = 0; j < 8; j++) s += part[((size_t)b * 8 + j) * AD + a];
    gq[b * AD + a] = s;
}

// ---------------------------------------------------------------------------
// gscores[b,s] = dot(gq[b,:], k[b,s,:]) / sqrt(AD)  (k inside qkv, stride 1536)
// ---------------------------------------------------------------------------
__global__ void __launch_bounds__(256) k_gscores(
    const __half* __restrict__ qkv, const float* __restrict__ gq, float* __restrict__ gs)
{
    int t = threadIdx.x;
    int key = blockIdx.x * 32 + (t >> 3);
    int lane = t & 7;
    int b = key / SS;
    int s = key % SS;
    const __half* krow = qkv + (size_t)key * NQKV + AD;
    const float* q = gq + b * AD;
    float sum = 0.f;
    for (int a = lane; a < AD; a += 8) sum += __half2float(krow[a]) * q[a];
#pragma unroll
    for (int o = 4; o > 0; o >>= 1) sum += __shfl_down_sync(0xffffffffu, sum, o, 8);
    if (lane == 0) gs[b * SS + s] = sum * rsqrtf((float)AD);
}

// ---------------------------------------------------------------------------
// In-place half softmax, rows of SS=2048. 256 threads; 8 halves/thread.
// ---------------------------------------------------------------------------
__global__ void __launch_bounds__(256) k_softmax_h(__half* __restrict__ data)
{
    uint4* row = (uint4*)(data + (size_t)blockIdx.x * SS);
    int t = threadIdx.x;
    uint4 u = row[t];
    __half2 h[4];
    memcpy(h, &u, 16);
    float v[8];
#pragma unroll
    for (int i = 0; i < 4; i++) {
        float2 f = __half22float2(h[i]);
        v[2 * i] = f.x; v[2 * i + 1] = f.y;
    }
    __shared__ float red[8];

    float m = v[0];
#pragma unroll
    for (int i = 1; i < 8; i++) m = fmaxf(m, v[i]);
#pragma unroll
    for (int o = 16; o > 0; o >>= 1) m = fmaxf(m, __shfl_xor_sync(0xffffffffu, m, o));
    if ((t & 31) == 0) red[t >> 5] = m;
    __syncthreads();
    m = red[0];
#pragma unroll
    for (int w = 1; w < 8; w++) m = fmaxf(m, red[w]);
    __syncthreads();

    float s = 0.f;
#pragma unroll
    for (int i = 0; i < 8; i++) { v[i] = __expf(v[i] - m); s += v[i]; }
#pragma unroll
    for (int o = 16; o > 0; o >>= 1) s += __shfl_xor_sync(0xffffffffu, s, o);
    if ((t & 31) == 0) red[t >> 5] = s;
    __syncthreads();
    float tot = 0.f;
#pragma unroll
    for (int w = 0; w < 8; w++) tot += red[w];
    float inv = 1.f / tot;

#pragma unroll
    for (int i = 0; i < 4; i++)
        h[i] = __floats2half2_rn(v[2 * i] * inv, v[2 * i + 1] * inv);
    memcpy(&u, h, 16);
    row[t] = u;
}

// ---------------------------------------------------------------------------
// fp32 softmax (for the tiny global-scores rows)
// ---------------------------------------------------------------------------
__global__ void __launch_bounds__(256) k_softmax_f(float* __restrict__ data)
{
    float4* row = (float4*)(data + (size_t)blockIdx.x * SS);
    int t = threadIdx.x;
    float4 v0 = row[t];
    float4 v1 = row[t + 256];
    __shared__ float red[8];

    float m = fmaxf(fmaxf(fmaxf(v0.x, v0.y), fmaxf(v0.z, v0.w)),
                    fmaxf(fmaxf(v1.x, v1.y), fmaxf(v1.z, v1.w)));
#pragma unroll
    for (int o = 16; o > 0; o >>= 1) m = fmaxf(m, __shfl_xor_sync(0xffffffffu, m, o));
    if ((t & 31) == 0) red[t >> 5] = m;
    __syncthreads();
    m = red[0];
#pragma unroll
    for (int w = 1; w < 8; w++) m = fmaxf(m, red[w]);
    __syncthreads();

    v0.x = __expf(v0.x - m); v0.y = __expf(v0.y - m);
    v0.z = __expf(v0.z - m); v0.w = __expf(v0.w - m);
    v1.x = __expf(v1.x - m); v1.y = __expf(v1.y - m);
    v1.z = __expf(v1.z - m); v1.w = __expf(v1.w - m);

    float s = (v0.x + v0.y + v0.z + v0.w) + (v1.x + v1.y + v1.z + v1.w);
#pragma unroll
    for (int o = 16; o > 0; o >>= 1) s += __shfl_xor_sync(0xffffffffu, s, o);
    if ((t & 31) == 0) red[t >> 5] = s;
    __syncthreads();
    float tot = 0.f;
#pragma unroll
    for (int w = 0; w < 8; w++) tot += red[w];
    float inv = 1.f / tot;

    v0.x *= inv; v0.y *= inv; v0.z *= inv; v0.w *= inv;
    v1.x *= inv; v1.y *= inv; v1.z *= inv; v1.w *= inv;
    row[t] = v0;
    row[t + 256] = v1;
}

// ---------------------------------------------------------------------------
// global_out two-stage (half v inside qkv, stride 1536)
// ---------------------------------------------------------------------------
__global__ void __launch_bounds__(128) k_gout_part(
    const float* __restrict__ gw, const __half* __restrict__ qkv, float* __restrict__ part)
{
    int a = blockIdx.x * 128 + threadIdx.x;
    int sc = blockIdx.y, b = blockIdx.z;
    const __half* vb = qkv + (size_t)b * SS * NQKV + (size_t)(sc * 128) * NQKV + 2 * AD + a;
    const float* w = gw + b * SS + sc * 128;
    float sum = 0.f;
#pragma unroll 4
    for (int s = 0; s < 128; s++) sum += w[s] * __half2float(vb[(size_t)s * NQKV]);
    part[((size_t)b * 16 + sc) * AD + a] = sum;
}
__global__ void __launch_bounds__(128) k_gout_red(
    const float* __restrict__ part, float* __restrict__ go)
{
    int a = blockIdx.x * 128 + threadIdx.x;
    int b = blockIdx.y;
    float s = 0.f;
#pragma unroll
    for (int j = 0; j < 16; j++) s += part[((size_t)b * 16 + j) * AD + a];
    go[b * AD + a] = s;
}

// ---------------------------------------------------------------------------
// LayerNorm in-place on HALF rows (len DD). 256 threads, 4 halves/thread.
// ---------------------------------------------------------------------------
__global__ void __launch_bounds__(256) k_ln_h(
    __half* __restrict__ y, const float* __restrict__ gamma, const float* __restrict__ beta)
{
    __half2* row = (__half2*)(y + (size_t)blockIdx.x * DD);
    int t = threadIdx.x;
    __half2 a = row[t];
    __half2 b = row[t + 256];
    float2 fa = __half22float2(a);
    float2 fb = __half22float2(b);
    float sum = fa.x + fa.y + fb.x + fb.y;
    float sq = fa.x * fa.x + fa.y * fa.y + fb.x * fb.x + fb.y * fb.y;

    __shared__ float r1[8], r2[8];
#pragma unroll
    for (int o = 16; o > 0; o >>= 1) {
        sum += __shfl_xor_sync(0xffffffffu, sum, o);
        sq += __shfl_xor_sync(0xffffffffu, sq, o);
    }
    if ((t & 31) == 0) { r1[t >> 5] = sum; r2[t >> 5] = sq; }
    __syncthreads();
    float ts = 0.f, tq = 0.f;
#pragma unroll
    for (int w = 0; w < 8; w++) { ts += r1[w]; tq += r2[w]; }
    float mu = ts * (1.f / DD);
    float var = tq * (1.f / DD) - mu * mu;
    float inv = rsqrtf(var + 1e-5f);

    int c0 = 2 * t, c1 = 2 * (t + 256);
    row[t] = __floats2half2_rn((fa.x - mu) * inv * gamma[c0] + beta[c0],
                               (fa.y - mu) * inv * gamma[c0 + 1] + beta[c0 + 1]);
    row[t + 256] = __floats2half2_rn((fb.x - mu) * inv * gamma[c1] + beta[c1],
                                     (fb.y - mu) * inv * gamma[c1 + 1] + beta[c1 + 1]);
}

// ---------------------------------------------------------------------------
// colmean two-stage (HALF weights -> fp32 partials)
// ---------------------------------------------------------------------------
__global__ void __launch_bounds__(256) k_colmean_part(
    const __half* __restrict__ wts, float* __restrict__ part)
{
    int s = blockIdx.x * 256 + threadIdx.x;
    int qc = blockIdx.y, b = blockIdx.z;
    const __half* base = wts + (size_t)b * SS * SS + (size_t)(qc * 256) * SS + s;
    float sum = 0.f;
#pragma unroll 4
    for (int q = 0; q < 256; q++) sum += __half2float(base[(size_t)q * SS]);
    part[((size_t)b * 8 + qc) * SS + s] = sum;
}
__global__ void __launch_bounds__(256) k_colmean_red(
    const float* __restrict__ part, const float* __restrict__ gw, float* __restrict__ avg)
{
    int s = blockIdx.x * 256 + threadIdx.x;
    int b = blockIdx.y;
    float sum = 0.f;
#pragma unroll
    for (int j = 0; j < 8; j++) sum += part[((size_t)b * 8 + j) * SS + s];
    avg[b * SS + s] = 0.7f * (sum * (1.f / SS)) + 0.3f * gw[b * SS + s];
}

// ---------------------------------------------------------------------------
// context two-stage (HALF y)
// ---------------------------------------------------------------------------
__global__ void __launch_bounds__(256) k_context_part(
    const float* __restrict__ avg, const __half* __restrict__ y, float* __restrict__ part)
{
    int d = blockIdx.x * 256 + threadIdx.x;
    int sc = blockIdx.y, b = blockIdx.z;
    const __half* yb = y + (size_t)b * SS * DD + (size_t)(sc * 128) * DD + d;
    const float* w = avg + b * SS + sc * 128;
    float sum = 0.f;
#pragma unroll 4
    for (int s = 0; s < 128; s++) sum += w[s] * __half2float(yb[(size_t)s * DD]);
    part[((size_t)b * 16 + sc) * DD + d] = sum;
}
__global__ void __launch_bounds__(256) k_context_red(
    const float* __restrict__ part, float* __restrict__ ctx)
{
    int d = blockIdx.x * 256 + threadIdx.x;
    int b = blockIdx.y;
    float s = 0.f;
#pragma unroll
    for (int j = 0; j < 16; j++) s += part[((size_t)b * 16 + j) * DD + d];
    ctx[b * DD + d] = s;
}

// ---------------------------------------------------------------------------

extern "C" void kernel_launch(void* const* d_in, const int* in_sizes, int n_in,
                              void* d_out, int out_size)
{
    const float* x     = (const float*)d_in[0];
    const float* gc    = (const float*)d_in[1];
    const float* Wq    = (const float*)d_in[2];
    const float* bq    = (const float*)d_in[3];
    const float* Wk    = (const float*)d_in[4];
    const float* bk    = (const float*)d_in[5];
    const float* Wv    = (const float*)d_in[6];
    const float* bv    = (const float*)d_in[7];
    const float* Wo    = (const float*)d_in[8];
    const float* bo    = (const float*)d_in[9];
    const float* gamma = (const float*)d_in[10];
    const float* beta  = (const float*)d_in[11];
    float* outp = (float*)d_out;

    float *pgq, *pgs, *pgo, *ppart, *pbqkv;
    __half *pxh, *pwqkvt, *pwot, *pqkv, *pvth, *pwh, *pwinh, *pyh;
    cudaGetSymbolAddress((void**)&pgq,   g_gq);
    cudaGetSymbolAddress((void**)&pgs,   g_gs);
    cudaGetSymbolAddress((void**)&pgo,   g_gout);
    cudaGetSymbolAddress((void**)&ppart, g_part);
    cudaGetSymbolAddress((void**)&pbqkv, g_bqkv);
    cudaGetSymbolAddress((void**)&pxh,   g_xh);
    cudaGetSymbolAddress((void**)&pwqkvt, g_wqkvt);
    cudaGetSymbolAddress((void**)&pwot,  g_wot);
    cudaGetSymbolAddress((void**)&pqkv,  g_qkv);
    cudaGetSymbolAddress((void**)&pvth,  g_vth);
    cudaGetSymbolAddress((void**)&pwh,   g_wh);
    cudaGetSymbolAddress((void**)&pwinh, g_winh);
    cudaGetSymbolAddress((void**)&pyh,   g_yh);

    cudaFuncSetAttribute(gemm_h<0>, cudaFuncAttributeMaxDynamicSharedMemorySize, GH_SMEM);
    cudaFuncSetAttribute(gemm_h<2>, cudaFuncAttributeMaxDynamicSharedMemorySize, GH_SMEM);
    cudaFuncSetAttribute(gemm_h<3>, cudaFuncAttributeMaxDynamicSharedMemorySize, GH_SMEM);
    cudaFuncSetAttribute(gemm_h<4>, cudaFuncAttributeMaxDynamicSharedMemorySize, GH_SMEM);

    const float scl = 1.0f / sqrtf((float)AD);
    const size_t strQKV = (size_t)SS * NQKV;
    const size_t strBSA = (size_t)SS * AD;
    const size_t strBSS = (size_t)SS * SS;

    // prep (x->half + bias concat) and weight transposes
    k_prep<<<(BB * SS * DD) / 1024, 256>>>((const float4*)x, pxh, bq, bk, bv, pbqkv);
    k_transpose_h<<<dim3(AD / 32, DD / 32), dim3(32, 8)>>>(Wq, pwqkvt, DD, AD);
    k_transpose_h<<<dim3(AD / 32, DD / 32), dim3(32, 8)>>>(Wk, pwqkvt + (size_t)AD * DD, DD, AD);
    k_transpose_h<<<dim3(AD / 32, DD / 32), dim3(32, 8)>>>(Wv, pwqkvt + (size_t)2 * AD * DD, DD, AD);

    // fused QKV projection: [16384,1024] x [1536,1024]^T -> qkv half
    gemm_h<0><<<dim3(NQKV / 128, (BB * SS) / 128, 1), 128, GH_SMEM>>>(
        pxh, pwqkvt, pqkv, DD, DD, DD, NQKV, 0, 0, 0, pbqkv, nullptr, 0.f);

    // Wo transpose
    k_transpose_h<<<dim3(DD / 32, AD / 32), dim3(32, 8)>>>(Wo, pwot, AD, DD);

    // v (half, inside qkv) -> vT half [a][s] per batch
    k_transpose_hh<<<dim3(AD / 32, SS / 32, BB), dim3(32, 8)>>>(
        pqkv + 2 * AD, pvth, SS, AD, NQKV, strQKV, strBSA);

    // global query projection (fp32)
    k_gq_part<<<dim3(AD / 128, 8, BB), 128>>>(gc, Wq, ppart);
    k_gq_red<<<dim3(AD / 128, BB), 128>>>(ppart, bq, pgq);

    // scores = q @ k^T / sqrt(A)  -> half
    gemm_h<2><<<dim3(SS / 128, SS / 128, BB), 128, GH_SMEM>>>(
        pqkv, pqkv + AD, pwh, AD, NQKV, NQKV, SS, strQKV, strQKV, strBSS,
        nullptr, nullptr, scl);

    // softmax in place on half scores
    k_softmax_h<<<BB * SS, 256>>>(pwh);

    // global scores + softmax (fp32)
    k_gscores<<<(BB * SS) / 32, 256>>>(pqkv, pgq, pgs);
    k_softmax_f<<<BB, 256>>>(pgs);

    // global_out (half v)
    k_gout_part<<<dim3(AD / 128, 16, BB), 128>>>(pgs, pqkv, ppart);
    k_gout_red<<<dim3(AD / 128, BB), 128>>>(ppart, pgo);

    // win = 0.7*weights@v + 0.3*gout   (128x128 tile — R12 config)
    gemm_h<3><<<dim3(AD / 128, SS / 128, BB), 128, GH_SMEM>>>(
        pwh, pvth, pwinh, SS, SS, SS, AD, strBSS, strBSA, strBSA,
        pgo, nullptr, 0.f);

    // y = x + win @ Wo + bo   (half out, half residual)
    gemm_h<4><<<dim3(DD / 128, (BB * SS) / 128, 1), 128, GH_SMEM>>>(
        pwinh, pwot, pyh, AD, AD, AD, DD, 0, 0, 0, bo, pxh, 0.f);

    // LayerNorm (half in/out)
    k_ln_h<<<BB * SS, 256>>>(pyh, gamma, beta);

    // avg_w (half weights)
    k_colmean_part<<<dim3(SS / 256, 8, BB), 256>>>(pwh, ppart);
    k_colmean_red<<<dim3(SS / 256, BB), 256>>>(ppart, pgs, outp + BB * DD);

    // context (half y)
    k_context_part<<<dim3(DD / 256, 16, BB), 256>>>(outp + BB * DD, pyh, ppart);
    k_context_red<<<dim3(DD / 256, BB), 256>>>(ppart, outp);
}

// round 17
// speedup vs baseline: 1.0406x; 1.0205x over previous
#include <cuda_runtime.h>
#include <cuda_fp16.h>
#include <math.h>
#include <stdint.h>

// Problem constants
#define BB 8
#define SS 2048
#define DD 1024
#define AD 512
#define NQKV 1536   // 3*AD concatenated q|k|v output columns

// ---------------------------------------------------------------------------
// Scratch (__device__ globals; allocation-free rule)
// ---------------------------------------------------------------------------
__device__ float  g_gq[BB * AD];
__device__ float  g_gs[BB * SS];
__device__ float  g_gout[BB * AD];
__device__ float  g_part[BB * 16 * SS];
__device__ float  g_bqkv[NQKV];

__device__ __half g_xh[BB * SS * DD];                 // half x
__device__ __half g_wqkvt[NQKV * DD];                 // [Wq|Wk|Wv]^T half [1536][1024]
__device__ __half g_wot[DD * AD];                     // Wo^T half [D][A]
__device__ __half g_qkv[(size_t)BB * SS * NQKV];      // q|k|v interleaved [b][s][1536]
__device__ __half g_vth[BB * SS * AD];                // V^T half [b][a][s]
__device__ __half g_wh[(size_t)BB * SS * SS];         // half softmax weights
__device__ __half g_winh[BB * SS * AD];
__device__ __half g_yh[BB * SS * DD];                 // half y (residual+LN)

// ---------------------------------------------------------------------------
// fp16 tensor-core GEMM, all-NT: C[m][n] = sum_k A[m][k] * B[n][k]
// Block 128x128, K-chunk 32, 128 threads (4 warps 2x2, warp tile 64x64).
// mma.sync.m16n8k16 fp32-accum, ldmatrix frag loads, 3-stage cp.async.
// EPI: 0 half out +e0[n]; 2 half out *scale;
//      3 half out 0.7*acc+0.3*e0[z*AD+n]; 4 half out +e0[n]+e1h[m*ldc+n]
// ---------------------------------------------------------------------------
#define HSTR 40                       // row stride in halves (80 B)
#define STG_H (128 * HSTR)            // halves per stage per operand
#define GH_SMEM (3 * STG_H * 2 * 2)   // 61440 B (3 stages, A+B, 2B/half)

__device__ __forceinline__ void cp16(void* s, const void* g) {
    uint32_t sa = (uint32_t)__cvta_generic_to_shared(s);
    asm volatile("cp.async.cg.shared.global [%0], [%1], 16;\n" :: "r"(sa), "l"(g));
}
#define LDSM4(r0, r1, r2, r3, a) \
    asm volatile("ldmatrix.sync.aligned.m8n8.x4.shared.b16 {%0,%1,%2,%3}, [%4];" \
                 : "=r"(r0), "=r"(r1), "=r"(r2), "=r"(r3) : "r"(a))

template <int EPI>
__global__ void __launch_bounds__(128, 3) gemm_h(
    const __half* __restrict__ Am, const __half* __restrict__ Bm,
    __half* __restrict__ Ch,
    int K, int lda, int ldb, int ldc,
    size_t sA, size_t sB, size_t sC,
    const float* __restrict__ e0, const __half* __restrict__ e1h, float scale)
{
    extern __shared__ __half sh[];
    __half* As = sh;                 // 3 stages x 128 x HSTR
    __half* Bs = sh + 3 * STG_H;

    const __half* Ap = Am + (size_t)blockIdx.z * sA;
    const __half* Bp = Bm + (size_t)blockIdx.z * sB;

    const int tid = threadIdx.x;
    const int wid = tid >> 5;
    const int lane = tid & 31;
    const int wm = wid >> 1;
    const int wn = wid & 1;
    const int g = lane >> 2;
    const int t = lane & 3;
    const int m0 = blockIdx.y * 128;
    const int n0 = blockIdx.x * 128;

    const int lrow = lane & 15;
    const int lcol = (lane >> 4) << 3;
    const uint32_t sAb = (uint32_t)__cvta_generic_to_shared(As);
    const uint32_t sBb = (uint32_t)__cvta_generic_to_shared(Bs);
    const uint32_t stageBytes = STG_H * 2;

    float acc[4][8][4];
#pragma unroll
    for (int i = 0; i < 4; i++)
#pragma unroll
        for (int j = 0; j < 8; j++)
#pragma unroll
            for (int c = 0; c < 4; c++) acc[i][j][c] = 0.f;

    auto copy_stage = [&](int st, int k0) {
#pragma unroll
        for (int i = 0; i < 4; i++) {
            int c = tid + 128 * i;
            int row = c >> 2, off = (c & 3) << 3;
            cp16(&As[st * STG_H + row * HSTR + off],
                 Ap + (size_t)(m0 + row) * lda + k0 + off);
        }
#pragma unroll
        for (int i = 0; i < 4; i++) {
            int c = tid + 128 * i;
            int row = c >> 2, off = (c & 3) << 3;
            cp16(&Bs[st * STG_H + row * HSTR + off],
                 Bp + (size_t)(n0 + row) * ldb + k0 + off);
        }
    };

    const int nk = K / 32;
    copy_stage(0, 0);
    asm volatile("cp.async.commit_group;\n");
    copy_stage(1, 32);
    asm volatile("cp.async.commit_group;\n");

    int cur = 0;
    for (int kt = 0; kt < nk; kt++) {
        if (kt + 1 < nk) asm volatile("cp.async.wait_group 1;\n");
        else             asm volatile("cp.async.wait_group 0;\n");
        __syncthreads();
        if (kt + 2 < nk) {
            int nx = cur + 2; if (nx >= 3) nx -= 3;
            copy_stage(nx, (kt + 2) * 32);
            asm volatile("cp.async.commit_group;\n");
        }
        uint32_t aBase = sAb + cur * stageBytes + ((wm * 64 + lrow) * HSTR + lcol) * 2;
        uint32_t bBase = sBb + cur * stageBytes + ((wn * 64 + lrow) * HSTR + lcol) * 2;
#pragma unroll
        for (int ks = 0; ks < 2; ks++) {
            const int kb = ks * 16;
            uint32_t afr[4][4];
#pragma unroll
            for (int mt = 0; mt < 4; mt++)
                LDSM4(afr[mt][0], afr[mt][1], afr[mt][2], afr[mt][3],
                      aBase + (mt * 16 * HSTR + kb) * 2);
#pragma unroll
            for (int p = 0; p < 4; p++) {
                uint32_t b00, b01, b10, b11;
                LDSM4(b00, b01, b10, b11, bBase + (p * 16 * HSTR + kb) * 2);
#pragma unroll
                for (int h = 0; h < 2; h++) {
                    int nt = p * 2 + h;
                    uint32_t b0 = h ? b01 : b00;
                    uint32_t b1 = h ? b11 : b10;
#pragma unroll
                    for (int mt = 0; mt < 4; mt++) {
                        asm volatile(
                            "mma.sync.aligned.m16n8k16.row.col.f32.f16.f16.f32 "
                            "{%0,%1,%2,%3}, {%4,%5,%6,%7}, {%8,%9}, {%0,%1,%2,%3};\n"
                            : "+f"(acc[mt][nt][0]), "+f"(acc[mt][nt][1]),
                              "+f"(acc[mt][nt][2]), "+f"(acc[mt][nt][3])
                            : "r"(afr[mt][0]), "r"(afr[mt][1]),
                              "r"(afr[mt][2]), "r"(afr[mt][3]),
                              "r"(b0), "r"(b1));
                    }
                }
            }
        }
        if (++cur == 3) cur = 0;
    }

    // Epilogue
#pragma unroll
    for (int mt = 0; mt < 4; mt++) {
#pragma unroll
        for (int nt = 0; nt < 8; nt++) {
            int row = m0 + wm * 64 + mt * 16 + g;
            int col = n0 + wn * 64 + nt * 8 + 2 * t;
#pragma unroll
            for (int h = 0; h < 2; h++) {
                int r = row + h * 8;
                float v0 = acc[mt][nt][h * 2 + 0];
                float v1 = acc[mt][nt][h * 2 + 1];
                __half* Cp = Ch + (size_t)blockIdx.z * sC;
                if (EPI == 0) {
                    v0 += e0[col]; v1 += e0[col + 1];
                } else if (EPI == 2) {
                    v0 *= scale; v1 *= scale;
                } else if (EPI == 3) {
                    v0 = 0.7f * v0 + 0.3f * e0[blockIdx.z * AD + col];
                    v1 = 0.7f * v1 + 0.3f * e0[blockIdx.z * AD + col + 1];
                } else {
                    __half2 res = *(const __half2*)&e1h[(size_t)r * ldc + col];
                    float2 rf = __half22float2(res);
                    v0 += e0[col]     + rf.x;
                    v1 += e0[col + 1] + rf.y;
                }
                *(__half2*)&Cp[(size_t)r * ldc + col] = __floats2half2_rn(v0, v1);
            }
        }
    }
}

// ---------------------------------------------------------------------------
// Prep: x f32 -> half AND concat bias vectors
// ---------------------------------------------------------------------------
__global__ void __launch_bounds__(256) k_prep(
    const float4* __restrict__ in, __half* __restrict__ out,
    const float* __restrict__ bq, const float* __restrict__ bk,
    const float* __restrict__ bv, float* __restrict__ bout)
{
    int i = blockIdx.x * 256 + threadIdx.x;
    float4 v = in[i];
    __half2* o = (__half2*)(out + (size_t)i * 4);
    o[0] = __floats2half2_rn(v.x, v.y);
    o[1] = __floats2half2_rn(v.z, v.w);
    if (i < NQKV) {
        float b = (i < AD) ? bq[i] : (i < 2 * AD) ? bk[i - AD] : bv[i - 2 * AD];
        bout[i] = b;
    }
}

// ---------------------------------------------------------------------------
// Transpose + convert: src f32 [R][C] -> dst half [C][R].  block (32,8)
// ---------------------------------------------------------------------------
__global__ void k_transpose_h(const float* __restrict__ src, __half* __restrict__ dst,
                              int R, int C)
{
    __shared__ float t[32][33];
    int c0 = blockIdx.x * 32, r0 = blockIdx.y * 32;
    int tx = threadIdx.x, ty = threadIdx.y;
#pragma unroll
    for (int i = 0; i < 32; i += 8)
        t[ty + i][tx] = src[(size_t)(r0 + ty + i) * C + c0 + tx];
    __syncthreads();
#pragma unroll
    for (int i = 0; i < 32; i += 8)
        dst[(size_t)(c0 + ty + i) * R + r0 + tx] = __float2half(t[tx][ty + i]);
}

// ---------------------------------------------------------------------------
// Half transpose: src half [R][srcLd] (+batch) -> dst half [C][R] (+batch)
// ---------------------------------------------------------------------------
__global__ void k_transpose_hh(const __half* __restrict__ src, __half* __restrict__ dst,
                               int R, int C, int srcLd, size_t sSrc, size_t sDst)
{
    __shared__ __half t[32][34];
    src += (size_t)blockIdx.z * sSrc;
    dst += (size_t)blockIdx.z * sDst;
    int c0 = blockIdx.x * 32, r0 = blockIdx.y * 32;
    int tx = threadIdx.x, ty = threadIdx.y;
#pragma unroll
    for (int i = 0; i < 32; i += 8)
        t[ty + i][tx] = src[(size_t)(r0 + ty + i) * srcLd + c0 + tx];
    __syncthreads();
#pragma unroll
    for (int i = 0; i < 32; i += 8)
        dst[(size_t)(c0 + ty + i) * R + r0 + tx] = t[tx][ty + i];
}

// ---------------------------------------------------------------------------
// gq two-stage (fp32 Wq)
// ---------------------------------------------------------------------------
__global__ void __launch_bounds__(128) k_gq_part(
    const float* __restrict__ gc, const float* __restrict__ W, float* __restrict__ part)
{
    int a = blockIdx.x * 128 + threadIdx.x;
    int dc = blockIdx.y, b = blockIdx.z;
    const float* gv = gc + (size_t)b * DD + dc * 128;
    const float* Wp = W + (size_t)(dc * 128) * AD + a;
    float s = 0.f;
#pragma unroll 4
    for (int d = 0; d < 128; d++) s += gv[d] * Wp[(size_t)d * AD];
    part[((size_t)b * 8 + dc) * AD + a] = s;
}
__global__ void __launch_bounds__(128) k_gq_red(
    const float* __restrict__ part, const float* __restrict__ bias, float* __restrict__ gq)
{
    int a = blockIdx.x * 128 + threadIdx.x;
    int b = blockIdx.y;
    float s = bias[a];
#pragma unroll
    for (int j = 0; j < 8; j++) s += part[((size_t)b * 8 + j) * AD + a];
    gq[b * AD + a] = s;
}

// ---------------------------------------------------------------------------
// gscores[b,s] = dot(gq[b,:], k[b,s,:]) / sqrt(AD)  (k inside qkv, stride 1536)
// ---------------------------------------------------------------------------
__global__ void __launch_bounds__(256) k_gscores(
    const __half* __restrict__ qkv, const float* __restrict__ gq, float* __restrict__ gs)
{
    int t = threadIdx.x;
    int key = blockIdx.x * 32 + (t >> 3);
    int lane = t & 7;
    int b = key / SS;
    int s = key % SS;
    const __half* krow = qkv + (size_t)key * NQKV + AD;
    const float* q = gq + b * AD;
    float sum = 0.f;
    for (int a = lane; a < AD; a += 8) sum += __half2float(krow[a]) * q[a];
#pragma unroll
    for (int o = 4; o > 0; o >>= 1) sum += __shfl_down_sync(0xffffffffu, sum, o, 8);
    if (lane == 0) gs[b * SS + s] = sum * rsqrtf((float)AD);
}

// ---------------------------------------------------------------------------
// In-place half softmax, rows of SS=2048. 256 threads; 8 halves/thread.
// ---------------------------------------------------------------------------
__global__ void __launch_bounds__(256) k_softmax_h(__half* __restrict__ data)
{
    uint4* row = (uint4*)(data + (size_t)blockIdx.x * SS);
    int t = threadIdx.x;
    uint4 u = row[t];
    __half2 h[4];
    memcpy(h, &u, 16);
    float v[8];
#pragma unroll
    for (int i = 0; i < 4; i++) {
        float2 f = __half22float2(h[i]);
        v[2 * i] = f.x; v[2 * i + 1] = f.y;
    }
    __shared__ float red[8];

    float m = v[0];
#pragma unroll
    for (int i = 1; i < 8; i++) m = fmaxf(m, v[i]);
#pragma unroll
    for (int o = 16; o > 0; o >>= 1) m = fmaxf(m, __shfl_xor_sync(0xffffffffu, m, o));
    if ((t & 31) == 0) red[t >> 5] = m;
    __syncthreads();
    m = red[0];
#pragma unroll
    for (int w = 1; w < 8; w++) m = fmaxf(m, red[w]);
    __syncthreads();

    float s = 0.f;
#pragma unroll
    for (int i = 0; i < 8; i++) { v[i] = __expf(v[i] - m); s += v[i]; }
#pragma unroll
    for (int o = 16; o > 0; o >>= 1) s += __shfl_xor_sync(0xffffffffu, s, o);
    if ((t & 31) == 0) red[t >> 5] = s;
    __syncthreads();
    float tot = 0.f;
#pragma unroll
    for (int w = 0; w < 8; w++) tot += red[w];
    float inv = 1.f / tot;

#pragma unroll
    for (int i = 0; i < 4; i++)
        h[i] = __floats2half2_rn(v[2 * i] * inv, v[2 * i + 1] * inv);
    memcpy(&u, h, 16);
    row[t] = u;
}

// ---------------------------------------------------------------------------
// fp32 softmax (for the tiny global-scores rows)
// ---------------------------------------------------------------------------
__global__ void __launch_bounds__(256) k_softmax_f(float* __restrict__ data)
{
    float4* row = (float4*)(data + (size_t)blockIdx.x * SS);
    int t = threadIdx.x;
    float4 v0 = row[t];
    float4 v1 = row[t + 256];
    __shared__ float red[8];

    float m = fmaxf(fmaxf(fmaxf(v0.x, v0.y), fmaxf(v0.z, v0.w)),
                    fmaxf(fmaxf(v1.x, v1.y), fmaxf(v1.z, v1.w)));
#pragma unroll
    for (int o = 16; o > 0; o >>= 1) m = fmaxf(m, __shfl_xor_sync(0xffffffffu, m, o));
    if ((t & 31) == 0) red[t >> 5] = m;
    __syncthreads();
    m = red[0];
#pragma unroll
    for (int w = 1; w < 8; w++) m = fmaxf(m, red[w]);
    __syncthreads();

    v0.x = __expf(v0.x - m); v0.y = __expf(v0.y - m);
    v0.z = __expf(v0.z - m); v0.w = __expf(v0.w - m);
    v1.x = __expf(v1.x - m); v1.y = __expf(v1.y - m);
    v1.z = __expf(v1.z - m); v1.w = __expf(v1.w - m);

    float s = (v0.x + v0.y + v0.z + v0.w) + (v1.x + v1.y + v1.z + v1.w);
#pragma unroll
    for (int o = 16; o > 0; o >>= 1) s += __shfl_xor_sync(0xffffffffu, s, o);
    if ((t & 31) == 0) red[t >> 5] = s;
    __syncthreads();
    float tot = 0.f;
#pragma unroll
    for (int w = 0; w < 8; w++) tot += red[w];
    float inv = 1.f / tot;

    v0.x *= inv; v0.y *= inv; v0.z *= inv; v0.w *= inv;
    v1.x *= inv; v1.y *= inv; v1.z *= inv; v1.w *= inv;
    row[t] = v0;
    row[t + 256] = v1;
}

// ---------------------------------------------------------------------------
// global_out two-stage (half v inside qkv, stride 1536)
// ---------------------------------------------------------------------------
__global__ void __launch_bounds__(128) k_gout_part(
    const float* __restrict__ gw, const __half* __restrict__ qkv, float* __restrict__ part)
{
    int a = blockIdx.x * 128 + threadIdx.x;
    int sc = blockIdx.y, b = blockIdx.z;
    const __half* vb = qkv + (size_t)b * SS * NQKV + (size_t)(sc * 128) * NQKV + 2 * AD + a;
    const float* w = gw + b * SS + sc * 128;
    float sum = 0.f;
#pragma unroll 4
    for (int s = 0; s < 128; s++) sum += w[s] * __half2float(vb[(size_t)s * NQKV]);
    part[((size_t)b * 16 + sc) * AD + a] = sum;
}
__global__ void __launch_bounds__(128) k_gout_red(
    const float* __restrict__ part, float* __restrict__ go)
{
    int a = blockIdx.x * 128 + threadIdx.x;
    int b = blockIdx.y;
    float s = 0.f;
#pragma unroll
    for (int j = 0; j < 16; j++) s += part[((size_t)b * 16 + j) * AD + a];
    go[b * AD + a] = s;
}

// ---------------------------------------------------------------------------
// LayerNorm in-place on HALF rows (len DD). 256 threads, 4 halves/thread.
// ---------------------------------------------------------------------------
__global__ void __launch_bounds__(256) k_ln_h(
    __half* __restrict__ y, const float* __restrict__ gamma, const float* __restrict__ beta)
{
    __half2* row = (__half2*)(y + (size_t)blockIdx.x * DD);
    int t = threadIdx.x;
    __half2 a = row[t];
    __half2 b = row[t + 256];
    float2 fa = __half22float2(a);
    float2 fb = __half22float2(b);
    float sum = fa.x + fa.y + fb.x + fb.y;
    float sq = fa.x * fa.x + fa.y * fa.y + fb.x * fb.x + fb.y * fb.y;

    __shared__ float r1[8], r2[8];
#pragma unroll
    for (int o = 16; o > 0; o >>= 1) {
        sum += __shfl_xor_sync(0xffffffffu, sum, o);
        sq += __shfl_xor_sync(0xffffffffu, sq, o);
    }
    if ((t & 31) == 0) { r1[t >> 5] = sum; r2[t >> 5] = sq; }
    __syncthreads();
    float ts = 0.f, tq = 0.f;
#pragma unroll
    for (int w = 0; w < 8; w++) { ts += r1[w]; tq += r2[w]; }
    float mu = ts * (1.f / DD);
    float var = tq * (1.f / DD) - mu * mu;
    float inv = rsqrtf(var + 1e-5f);

    int c0 = 2 * t, c1 = 2 * (t + 256);
    row[t] = __floats2half2_rn((fa.x - mu) * inv * gamma[c0] + beta[c0],
                               (fa.y - mu) * inv * gamma[c0 + 1] + beta[c0 + 1]);
    row[t + 256] = __floats2half2_rn((fb.x - mu) * inv * gamma[c1] + beta[c1],
                                     (fb.y - mu) * inv * gamma[c1 + 1] + beta[c1 + 1]);
}

// ---------------------------------------------------------------------------
// colmean two-stage (HALF weights -> fp32 partials)
// ---------------------------------------------------------------------------
__global__ void __launch_bounds__(256) k_colmean_part(
    const __half* __restrict__ wts, float* __restrict__ part)
{
    int s = blockIdx.x * 256 + threadIdx.x;
    int qc = blockIdx.y, b = blockIdx.z;
    const __half* base = wts + (size_t)b * SS * SS + (size_t)(qc * 256) * SS + s;
    float sum = 0.f;
#pragma unroll 4
    for (int q = 0; q < 256; q++) sum += __half2float(base[(size_t)q * SS]);
    part[((size_t)b * 8 + qc) * SS + s] = sum;
}
__global__ void __launch_bounds__(256) k_colmean_red(
    const float* __restrict__ part, const float* __restrict__ gw, float* __restrict__ avg)
{
    int s = blockIdx.x * 256 + threadIdx.x;
    int b = blockIdx.y;
    float sum = 0.f;
#pragma unroll
    for (int j = 0; j < 8; j++) sum += part[((size_t)b * 8 + j) * SS + s];
    avg[b * SS + s] = 0.7f * (sum * (1.f / SS)) + 0.3f * gw[b * SS + s];
}

// ---------------------------------------------------------------------------
// context two-stage (HALF y)
// ---------------------------------------------------------------------------
__global__ void __launch_bounds__(256) k_context_part(
    const float* __restrict__ avg, const __half* __restrict__ y, float* __restrict__ part)
{
    int d = blockIdx.x * 256 + threadIdx.x;
    int sc = blockIdx.y, b = blockIdx.z;
    const __half* yb = y + (size_t)b * SS * DD + (size_t)(sc * 128) * DD + d;
    const float* w = avg + b * SS + sc * 128;
    float sum = 0.f;
#pragma unroll 4
    for (int s = 0; s < 128; s++) sum += w[s] * __half2float(yb[(size_t)s * DD]);
    part[((size_t)b * 16 + sc) * DD + d] = sum;
}
__global__ void __launch_bounds__(256) k_context_red(
    const float* __restrict__ part, float* __restrict__ ctx)
{
    int d = blockIdx.x * 256 + threadIdx.x;
    int b = blockIdx.y;
    float s = 0.f;
#pragma unroll
    for (int j = 0; j < 16; j++) s += part[((size_t)b * 16 + j) * DD + d];
    ctx[b * DD + d] = s;
}

// ---------------------------------------------------------------------------

extern "C" void kernel_launch(void* const* d_in, const int* in_sizes, int n_in,
                              void* d_out, int out_size)
{
    const float* x     = (const float*)d_in[0];
    const float* gc    = (const float*)d_in[1];
    const float* Wq    = (const float*)d_in[2];
    const float* bq    = (const float*)d_in[3];
    const float* Wk    = (const float*)d_in[4];
    const float* bk    = (const float*)d_in[5];
    const float* Wv    = (const float*)d_in[6];
    const float* bv    = (const float*)d_in[7];
    const float* Wo    = (const float*)d_in[8];
    const float* bo    = (const float*)d_in[9];
    const float* gamma = (const float*)d_in[10];
    const float* beta  = (const float*)d_in[11];
    float* outp = (float*)d_out;

    float *pgq, *pgs, *pgo, *ppart, *pbqkv;
    __half *pxh, *pwqkvt, *pwot, *pqkv, *pvth, *pwh, *pwinh, *pyh;
    cudaGetSymbolAddress((void**)&pgq,   g_gq);
    cudaGetSymbolAddress((void**)&pgs,   g_gs);
    cudaGetSymbolAddress((void**)&pgo,   g_gout);
    cudaGetSymbolAddress((void**)&ppart, g_part);
    cudaGetSymbolAddress((void**)&pbqkv, g_bqkv);
    cudaGetSymbolAddress((void**)&pxh,   g_xh);
    cudaGetSymbolAddress((void**)&pwqkvt, g_wqkvt);
    cudaGetSymbolAddress((void**)&pwot,  g_wot);
    cudaGetSymbolAddress((void**)&pqkv,  g_qkv);
    cudaGetSymbolAddress((void**)&pvth,  g_vth);
    cudaGetSymbolAddress((void**)&pwh,   g_wh);
    cudaGetSymbolAddress((void**)&pwinh, g_winh);
    cudaGetSymbolAddress((void**)&pyh,   g_yh);

    cudaFuncSetAttribute(gemm_h<0>, cudaFuncAttributeMaxDynamicSharedMemorySize, GH_SMEM);
    cudaFuncSetAttribute(gemm_h<2>, cudaFuncAttributeMaxDynamicSharedMemorySize, GH_SMEM);
    cudaFuncSetAttribute(gemm_h<3>, cudaFuncAttributeMaxDynamicSharedMemorySize, GH_SMEM);
    cudaFuncSetAttribute(gemm_h<4>, cudaFuncAttributeMaxDynamicSharedMemorySize, GH_SMEM);

    const float scl = 1.0f / sqrtf((float)AD);
    const size_t strQKV = (size_t)SS * NQKV;
    const size_t strBSA = (size_t)SS * AD;
    const size_t strBSS = (size_t)SS * SS;

    // Side stream + fork/join events (host-side ops; capture-legal).
    cudaStream_t s1;
    cudaStreamCreateWithFlags(&s1, cudaStreamNonBlocking);
    cudaEvent_t evFork, evJoin;
    cudaEventCreateWithFlags(&evFork, cudaEventDisableTiming);
    cudaEventCreateWithFlags(&evJoin, cudaEventDisableTiming);

    // ---- main stream (default): prep, W transposes, QKV GEMM ----
    k_prep<<<(BB * SS * DD) / 1024, 256>>>((const float4*)x, pxh, bq, bk, bv, pbqkv);
    k_transpose_h<<<dim3(AD / 32, DD / 32), dim3(32, 8)>>>(Wq, pwqkvt, DD, AD);
    k_transpose_h<<<dim3(AD / 32, DD / 32), dim3(32, 8)>>>(Wk, pwqkvt + (size_t)AD * DD, DD, AD);
    k_transpose_h<<<dim3(AD / 32, DD / 32), dim3(32, 8)>>>(Wv, pwqkvt + (size_t)2 * AD * DD, DD, AD);

    gemm_h<0><<<dim3(NQKV / 128, (BB * SS) / 128, 1), 128, GH_SMEM>>>(
        pxh, pwqkvt, pqkv, DD, DD, DD, NQKV, 0, 0, 0, pbqkv, nullptr, 0.f);

    // fork: side chain depends only on qkv
    cudaEventRecord(evFork, 0);
    cudaStreamWaitEvent(s1, evFork, 0);

    // ---- side stream: Wo transpose, vT, global-attention chain ----
    k_transpose_h<<<dim3(DD / 32, AD / 32), dim3(32, 8), 0, s1>>>(Wo, pwot, AD, DD);
    k_transpose_hh<<<dim3(AD / 32, SS / 32, BB), dim3(32, 8), 0, s1>>>(
        pqkv + 2 * AD, pvth, SS, AD, NQKV, strQKV, strBSA);
    k_gq_part<<<dim3(AD / 128, 8, BB), 128, 0, s1>>>(gc, Wq, ppart);
    k_gq_red<<<dim3(AD / 128, BB), 128, 0, s1>>>(ppart, bq, pgq);
    k_gscores<<<(BB * SS) / 32, 256, 0, s1>>>(pqkv, pgq, pgs);
    k_softmax_f<<<BB, 256, 0, s1>>>(pgs);
    k_gout_part<<<dim3(AD / 128, 16, BB), 128, 0, s1>>>(pgs, pqkv, ppart);
    k_gout_red<<<dim3(AD / 128, BB), 128, 0, s1>>>(ppart, pgo);
    cudaEventRecord(evJoin, s1);

    // ---- main stream meanwhile: scores GEMM + softmax ----
    gemm_h<2><<<dim3(SS / 128, SS / 128, BB), 128, GH_SMEM>>>(
        pqkv, pqkv + AD, pwh, AD, NQKV, NQKV, SS, strQKV, strQKV, strBSS,
        nullptr, nullptr, scl);
    k_softmax_h<<<BB * SS, 256>>>(pwh);

    // join before win GEMM (needs pvth + pgo from side chain)
    cudaStreamWaitEvent(0, evJoin, 0);

    // win = 0.7*weights@v + 0.3*gout
    gemm_h<3><<<dim3(AD / 128, SS / 128, BB), 128, GH_SMEM>>>(
        pwh, pvth, pwinh, SS, SS, SS, AD, strBSS, strBSA, strBSA,
        pgo, nullptr, 0.f);

    // y = x + win @ Wo + bo   (half out, half residual)
    gemm_h<4><<<dim3(DD / 128, (BB * SS) / 128, 1), 128, GH_SMEM>>>(
        pwinh, pwot, pyh, AD, AD, AD, DD, 0, 0, 0, bo, pxh, 0.f);

    // LayerNorm (half in/out)
    k_ln_h<<<BB * SS, 256>>>(pyh, gamma, beta);

    // avg_w (half weights; ppart free after side chain joined)
    k_colmean_part<<<dim3(SS / 256, 8, BB), 256>>>(pwh, ppart);
    k_colmean_red<<<dim3(SS / 256, BB), 256>>>(ppart, pgs, outp + BB * DD);

    // context (half y)
    k_context_part<<<dim3(DD / 256, 16, BB), 256>>>(outp + BB * DD, pyh, ppart);
    k_context_red<<<dim3(DD / 256, BB), 256>>>(ppart, outp);

    cudaEventDestroy(evFork);
    cudaEventDestroy(evJoin);
    cudaStreamDestroy(s1);
}